// round 11
// baseline (speedup 1.0000x reference)
#include <cuda_runtime.h>
#include <cuda_bf16.h>
#include <cstdint>

#define BB 2
#define HH 16
#define SS 2048
#define DD 64
#define NTHREADS 256
#define CTX_ELEMS (BB*HH*SS*DD)
#define NHEADS 32
#define NKT 16                 // key tiles of 128
#define TILE_BYTES 32768       // frag-tile image (hi+lo packed)
#define SMEM_TOTAL (131072 + 512)
#define EXPC 0.18033688011112042f   // 0.125 * log2(e)
#define MASK_WORDS (BB*SS*64)       // 262144 u32 words

// gmem scratch: fragment-ordered bf16 hi/lo images
__device__ __align__(16) unsigned char g_qf[(size_t)NHEADS*16*TILE_BYTES];
__device__ __align__(16) unsigned char g_kf[(size_t)NHEADS*NKT*TILE_BYTES];
__device__ __align__(16) unsigned char g_vf[(size_t)NHEADS*NKT*TILE_BYTES];
__device__ __align__(16) unsigned int  g_maskbits[MASK_WORDS];   // 1 bit per mask elem

__device__ __forceinline__ uint32_t pack2hi(float a, float b) {
    __nv_bfloat16 ha = __float2bfloat16(a), hb = __float2bfloat16(b);
    return (uint32_t)__bfloat16_as_ushort(ha) | ((uint32_t)__bfloat16_as_ushort(hb) << 16);
}
__device__ __forceinline__ uint32_t pack2lo(float a, float b) {
    __nv_bfloat16 ha = __float2bfloat16(a), hb = __float2bfloat16(b);
    __nv_bfloat16 la = __float2bfloat16(a - __bfloat162float(ha));
    __nv_bfloat16 lb = __float2bfloat16(b - __bfloat162float(hb));
    return (uint32_t)__bfloat16_as_ushort(la) | ((uint32_t)__bfloat16_as_ushort(lb) << 16);
}

// ---- merged prepass: fragment images (blocks 0..1535) + mask bits (1536..2559) ----
__global__ void prepass_kernel(const float* __restrict__ Q,
                               const float* __restrict__ K,
                               const float* __restrict__ V,
                               const int* __restrict__ M)
{
    const int bx = blockIdx.x;
    if (bx >= 1536) {
        const int w = (bx - 1536) * NTHREADS + threadIdx.x;   // 262144 words total
        const int* src = M + (size_t)w * 32;
        unsigned int bits = 0;
        #pragma unroll
        for (int j = 0; j < 32; j++) bits |= (src[j] != 0 ? 1u : 0u) << j;
        g_maskbits[w] = bits;
        return;
    }
    const int which = bx >> 9;               // 0=Q 1=K 2=V
    const int chunk = bx & 511;              // head*16 + sub
    const int head = chunk >> 4, sub = chunk & 15;
    const float* S_ = (which == 0 ? Q : which == 1 ? K : V) + (size_t)head * SS * DD;
    unsigned char* dst = (which == 0 ? g_qf : which == 1 ? g_kf : g_vf) + (size_t)chunk * TILE_BYTES;

    for (int i = threadIdx.x; i < 8192; i += NTHREADS) {
        float f0, f1; bool lo;
        if (which == 0) {
            int word = i & 7, lane = (i >> 3) & 31, kt = (i >> 8) & 3, mt = i >> 10;
            int ai = word & 3; lo = word >= 4;
            int r = (lane >> 2) + ((ai & 1) ? 8 : 0);
            int c = (lane & 3) * 2 + ((ai >= 2) ? 8 : 0);
            int row = sub * 128 + mt * 16 + r, col = kt * 16 + c;
            f0 = S_[(size_t)row * DD + col]; f1 = S_[(size_t)row * DD + col + 1];
        } else if (which == 1) {
            int word = i & 3, lane = (i >> 2) & 31, kt = (i >> 7) & 3, ntl = (i >> 9) & 15;
            int bsel = word & 1; lo = word >= 2;
            int key = (sub * 16 + ntl) * 8 + (lane >> 2);
            int dim = kt * 16 + (lane & 3) * 2 + (bsel ? 8 : 0);
            f0 = S_[(size_t)key * DD + dim]; f1 = S_[(size_t)key * DD + dim + 1];
        } else {
            int word = i & 3, lane = (i >> 2) & 31, ktl = (i >> 7) & 7, nt = (i >> 10) & 7;
            int bsel = word & 1; lo = word >= 2;
            int key = (sub * 8 + ktl) * 16 + (lane & 3) * 2 + (bsel ? 8 : 0);
            int dim = nt * 8 + (lane >> 2);
            f0 = S_[(size_t)key * DD + dim]; f1 = S_[(size_t)(key + 1) * DD + dim];
        }
        ((uint32_t*)dst)[i] = lo ? pack2lo(f0, f1) : pack2hi(f0, f1);
    }
}

// ---- main ----
__device__ __forceinline__ uint32_t smem_u32(const void* p) {
    uint32_t a;
    asm("{ .reg .u64 t; cvta.to.shared.u64 t, %1; cvt.u32.u64 %0, t; }" : "=r"(a) : "l"(p));
    return a;
}
__device__ __forceinline__ void cp16(uint32_t s, const void* g) {
    asm volatile("cp.async.cg.shared.global [%0], [%1], 16;" :: "r"(s), "l"(g));
}
__device__ __forceinline__ void mma_bf16(float d[4], const uint32_t a[4],
                                         uint32_t b0, uint32_t b1) {
    asm volatile("mma.sync.aligned.m16n8k16.row.col.f32.bf16.bf16.f32 "
        "{%0,%1,%2,%3}, {%4,%5,%6,%7}, {%8,%9}, {%0,%1,%2,%3};"
        : "+f"(d[0]), "+f"(d[1]), "+f"(d[2]), "+f"(d[3])
        : "r"(a[0]), "r"(a[1]), "r"(a[2]), "r"(a[3]), "r"(b0), "r"(b1));
}

// QK for a pair (j, j+1) with 4 independent accumulator chains.
// On return: dj = scores for column pair j, dk = for j+1.
__device__ __forceinline__ void qk_pair(const unsigned char* Kb, int lane, int j,
                                        const uint32_t qh[4][4], const uint32_t ql[4][4],
                                        float dj[4], float dk[4])
{
    float da[4] = {0.f,0.f,0.f,0.f}, db[4] = {0.f,0.f,0.f,0.f};
    float dc[4] = {0.f,0.f,0.f,0.f}, de[4] = {0.f,0.f,0.f,0.f};
    #pragma unroll
    for (int kt = 0; kt < 4; kt++) {
        uint4 b0 = *(const uint4*)(Kb + ((j * 4 + kt) * 32 + lane) * 16);
        uint4 b1 = *(const uint4*)(Kb + (((j + 1) * 4 + kt) * 32 + lane) * 16);
        mma_bf16(da, qh[kt], b0.x, b0.y);
        mma_bf16(dc, qh[kt], b1.x, b1.y);
        mma_bf16(db, ql[kt], b0.x, b0.y);
        mma_bf16(de, ql[kt], b1.x, b1.y);
        mma_bf16(db, qh[kt], b0.z, b0.w);
        mma_bf16(de, qh[kt], b1.z, b1.w);
    }
    #pragma unroll
    for (int i = 0; i < 4; i++) { dj[i] = da[i] + db[i]; dk[i] = dc[i] + de[i]; }
}

__global__ __launch_bounds__(NTHREADS)
void attn_main(float* __restrict__ out)
{
    extern __shared__ unsigned char smem[];   // K ping/pong 0/32K, V ping/pong 64K/96K, sums @128K
    float* sSum = (float*)(smem + 131072);
    const uint32_t sb = smem_u32(smem);
    const int tid = threadIdx.x, w = tid >> 5, lane = tid & 31;
    const int head = blockIdx.x >> 4, qblk = blockIdx.x & 15;
    const int b = head >> 4;
    const int q0 = qblk * 128;
    const int r0 = 16 * w + (lane >> 2);      // local row (this lane: r0 and r0+8)
    const int cq = (lane & 3) * 2;

    // Q fragments resident
    uint32_t qh[4][4], ql[4][4];
    {
        const unsigned char* qc = g_qf + (size_t)(head * 16 + qblk) * TILE_BYTES;
        #pragma unroll
        for (int kt = 0; kt < 4; kt++) {
            const unsigned char* p = qc + (size_t)(((w * 4 + kt) * 32 + lane) * 32);
            uint4 h = *(const uint4*)p, l = *(const uint4*)(p + 16);
            qh[kt][0] = h.x; qh[kt][1] = h.y; qh[kt][2] = h.z; qh[kt][3] = h.w;
            ql[kt][0] = l.x; ql[kt][1] = l.y; ql[kt][2] = l.z; ql[kt][3] = l.w;
        }
    }
    const unsigned char* mrow0 = (const unsigned char*)g_maskbits + (size_t)(b * SS + q0 + r0) * 256;
    const unsigned char* mrow1 = mrow0 + 8 * 256;
    const unsigned char* kbase = g_kf + (size_t)head * NKT * TILE_BYTES;
    const unsigned char* vbase = g_vf + (size_t)head * NKT * TILE_BYTES;

    // ================= pass A: row sums =================
    {
        const unsigned char* src = kbase;
        #pragma unroll
        for (int i = 0; i < 8; i++) cp16(sb + tid * 16 + i * 4096, src + tid * 16 + i * 4096);
        asm volatile("cp.async.commit_group;");
    }
    float rs0 = 0.f, rs1 = 0.f;
    for (int t = 0; t < 16; t++) {
        if (t < 15) {
            const unsigned char* src = kbase + (size_t)(t + 1) * TILE_BYTES;
            uint32_t d0 = sb + ((t + 1) & 1) * 32768;
            #pragma unroll
            for (int i = 0; i < 8; i++) cp16(d0 + tid * 16 + i * 4096, src + tid * 16 + i * 4096);
            asm volatile("cp.async.commit_group;");
            asm volatile("cp.async.wait_group 1;");
        } else {
            asm volatile("cp.async.wait_group 0;");
        }
        __syncthreads();
        const unsigned char* Kb = smem + (t & 1) * 32768;
        uint4 mA = *(const uint4*)(mrow0 + t * 16);
        uint4 mB = *(const uint4*)(mrow1 + t * 16);
        const uint32_t mwA[4] = {mA.x, mA.y, mA.z, mA.w};
        const uint32_t mwB[4] = {mB.x, mB.y, mB.z, mB.w};
        #pragma unroll
        for (int j = 0; j < 16; j += 2) {
            float dj[4], dk[4];
            qk_pair(Kb, lane, j, qh, ql, dj, dk);
            const int sh = 8 * (j & 3) + cq;
            const uint32_t maj = mwA[j >> 2] >> sh,       mbj = mwB[j >> 2] >> sh;
            const uint32_t mak = mwA[j >> 2] >> (sh + 8), mbk = mwB[j >> 2] >> (sh + 8);
            rs0 += ((maj & 1) ? 0.f : exp2f(dj[0] * EXPC)) + ((maj & 2) ? 0.f : exp2f(dj[1] * EXPC));
            rs1 += ((mbj & 1) ? 0.f : exp2f(dj[2] * EXPC)) + ((mbj & 2) ? 0.f : exp2f(dj[3] * EXPC));
            rs0 += ((mak & 1) ? 0.f : exp2f(dk[0] * EXPC)) + ((mak & 2) ? 0.f : exp2f(dk[1] * EXPC));
            rs1 += ((mbk & 1) ? 0.f : exp2f(dk[2] * EXPC)) + ((mbk & 2) ? 0.f : exp2f(dk[3] * EXPC));
        }
        __syncthreads();
    }
    rs0 += __shfl_xor_sync(0xFFFFFFFFu, rs0, 1); rs0 += __shfl_xor_sync(0xFFFFFFFFu, rs0, 2);
    rs1 += __shfl_xor_sync(0xFFFFFFFFu, rs1, 1); rs1 += __shfl_xor_sync(0xFFFFFFFFu, rs1, 2);
    if ((lane & 3) == 0) { sSum[r0] = rs0; sSum[r0 + 8] = rs1; }
    __syncthreads();
    const float inv0 = 1.0f / sSum[r0];
    const float inv1 = 1.0f / sSum[r0 + 8];

    // ================= pass B: recompute, write att, PV =================
    float dacc[8][4];
    #pragma unroll
    for (int nt = 0; nt < 8; nt++) { dacc[nt][0]=0.f; dacc[nt][1]=0.f; dacc[nt][2]=0.f; dacc[nt][3]=0.f; }
    {
        #pragma unroll
        for (int i = 0; i < 8; i++) cp16(sb + tid * 16 + i * 4096, kbase + tid * 16 + i * 4096);
        #pragma unroll
        for (int i = 0; i < 8; i++) cp16(sb + 65536 + tid * 16 + i * 4096, vbase + tid * 16 + i * 4096);
        asm volatile("cp.async.commit_group;");
    }
    float* att = out + (size_t)CTX_ELEMS + (size_t)head * SS * SS;
    for (int t = 0; t < 16; t++) {
        if (t < 15) {
            const unsigned char* sk = kbase + (size_t)(t + 1) * TILE_BYTES;
            const unsigned char* sv = vbase + (size_t)(t + 1) * TILE_BYTES;
            uint32_t dk_ = sb + ((t + 1) & 1) * 32768;
            uint32_t dv_ = sb + 65536 + ((t + 1) & 1) * 32768;
            #pragma unroll
            for (int i = 0; i < 8; i++) cp16(dk_ + tid * 16 + i * 4096, sk + tid * 16 + i * 4096);
            #pragma unroll
            for (int i = 0; i < 8; i++) cp16(dv_ + tid * 16 + i * 4096, sv + tid * 16 + i * 4096);
            asm volatile("cp.async.commit_group;");
            asm volatile("cp.async.wait_group 1;");
        } else {
            asm volatile("cp.async.wait_group 0;");
        }
        __syncthreads();
        const unsigned char* Kb = smem + (t & 1) * 32768;
        const unsigned char* Vb = smem + 65536 + (t & 1) * 32768;
        uint4 mA = *(const uint4*)(mrow0 + t * 16);
        uint4 mB = *(const uint4*)(mrow1 + t * 16);
        const uint32_t mwA[4] = {mA.x, mA.y, mA.z, mA.w};
        const uint32_t mwB[4] = {mB.x, mB.y, mB.z, mB.w};
        uint32_t eh[8][4], el[8][4];
        #pragma unroll
        for (int j = 0; j < 16; j += 2) {
            float dj[4], dk[4];
            qk_pair(Kb, lane, j, qh, ql, dj, dk);
            const int sh = 8 * (j & 3) + cq;
            const uint32_t maj = mwA[j >> 2] >> sh,       mbj = mwB[j >> 2] >> sh;
            const uint32_t mak = mwA[j >> 2] >> (sh + 8), mbk = mwB[j >> 2] >> (sh + 8);
            float p0 = (maj & 1) ? 0.f : exp2f(dj[0] * EXPC) * inv0;
            float p1 = (maj & 2) ? 0.f : exp2f(dj[1] * EXPC) * inv0;
            float p2 = (mbj & 1) ? 0.f : exp2f(dj[2] * EXPC) * inv1;
            float p3 = (mbj & 2) ? 0.f : exp2f(dj[3] * EXPC) * inv1;
            float p4 = (mak & 1) ? 0.f : exp2f(dk[0] * EXPC) * inv0;
            float p5 = (mak & 2) ? 0.f : exp2f(dk[1] * EXPC) * inv0;
            float p6 = (mbk & 1) ? 0.f : exp2f(dk[2] * EXPC) * inv1;
            float p7 = (mbk & 2) ? 0.f : exp2f(dk[3] * EXPC) * inv1;
            // attention output (normalized probs)
            float* a0 = att + (size_t)(q0 + r0) * SS + t * 128 + 8 * j + cq;
            *(float2*)a0 = make_float2(p0, p1);
            *(float2*)(a0 + 8 * (size_t)SS) = make_float2(p2, p3);
            *(float2*)(a0 + 8) = make_float2(p4, p5);
            *(float2*)(a0 + 8 * (size_t)SS + 8) = make_float2(p6, p7);
            // E fragments for PV (D layout == A layout); pair fills one u slot
            const int u = j >> 1;
            eh[u][0] = pack2hi(p0, p1); eh[u][1] = pack2hi(p2, p3);
            el[u][0] = pack2lo(p0, p1); el[u][1] = pack2lo(p2, p3);
            eh[u][2] = pack2hi(p4, p5); eh[u][3] = pack2hi(p6, p7);
            el[u][2] = pack2lo(p4, p5); el[u][3] = pack2lo(p6, p7);
        }
        #pragma unroll
        for (int ktl = 0; ktl < 8; ktl++) {
            #pragma unroll
            for (int nt = 0; nt < 8; nt++) {
                uint4 vb = *(const uint4*)(Vb + ((nt * 8 + ktl) * 32 + lane) * 16);
                mma_bf16(dacc[nt], eh[ktl], vb.x, vb.y);
                mma_bf16(dacc[nt], el[ktl], vb.x, vb.y);
                mma_bf16(dacc[nt], eh[ktl], vb.z, vb.w);
            }
        }
        __syncthreads();
    }

    // context epilogue
    float* ctx = out + (size_t)head * SS * DD;
    #pragma unroll
    for (int nt = 0; nt < 8; nt++) {
        const int col = 8 * nt + cq;
        *(float2*)(ctx + (size_t)(q0 + r0) * DD + col)     = make_float2(dacc[nt][0], dacc[nt][1]);
        *(float2*)(ctx + (size_t)(q0 + r0 + 8) * DD + col) = make_float2(dacc[nt][2], dacc[nt][3]);
    }
}

extern "C" void kernel_launch(void* const* d_in, const int* in_sizes, int n_in,
                              void* d_out, int out_size)
{
    (void)in_sizes; (void)n_in; (void)out_size;
    const float* Q = (const float*)d_in[0];
    const float* K = (const float*)d_in[1];
    const float* V = (const float*)d_in[2];
    const int*   M = (const int*)d_in[3];
    float* out = (float*)d_out;

    cudaFuncSetAttribute(attn_main,
                         cudaFuncAttributeMaxDynamicSharedMemorySize, SMEM_TOTAL);

    prepass_kernel<<<2560, NTHREADS>>>(Q, K, V, M);
    attn_main<<<NHEADS * 16, NTHREADS, SMEM_TOTAL>>>(out);
}